// round 7
// baseline (speedup 1.0000x reference)
#include <cuda_runtime.h>

// dim=4096, MAX_DIM=32, N_COMP=10000.
// gather_idx/gather_sign: [32,32,32] row-major (k,i,j), int32/float32.
// Output: ricci[4096*4096] row-major + scalar trace at index 4096*4096.

#define DIMN 4096
#define MD   32
#define NV4  (DIMN * DIMN / 4)          // 4,194,304 float4 chunks
#define GRID 2048
#define TPB  256
#define CPB  (NV4 / GRID)               // 2048 chunks per block (32 KB)
#define ITERS (CPB / TPB)               // 8 stores per thread

__global__ __launch_bounds__(TPB)
void ricci_fused2_kernel(const float* __restrict__ comp,
                         const int*   __restrict__ gidx,
                         const float* __restrict__ gsgn,
                         float* __restrict__ out)
{
    float4* __restrict__ out4 = reinterpret_cast<float4*>(out);
    const unsigned base = blockIdx.x * CPB + threadIdx.x;

    #pragma unroll
    for (int it = 0; it < ITERS; it++) {
        const unsigned idx = base + it * TPB;   // float4 index, block-contiguous
        float4 v = make_float4(0.f, 0.f, 0.f, 0.f);

        // Patch region: rows 0..31, cols 0..31 -> idx < 32*1024 and
        // (idx % 1024) < 8. Only blocks 0..15 can hit this (16 chunks each).
        if (idx < (MD * DIMN / 4) && (idx & (DIMN / 4 - 1)) < (MD / 4)) {
            const int i = idx >> 10;            // row
            const int j = (idx & 1023) << 2;    // col base
            float r0 = 0.f, r1 = 0.f, r2 = 0.f, r3 = 0.f;
            #pragma unroll
            for (int k = 0; k < MD; k++) {
                const int o = k * (MD * MD) + i * MD + j;
                r0 += gsgn[o + 0] * comp[gidx[o + 0]];
                r1 += gsgn[o + 1] * comp[gidx[o + 1]];
                r2 += gsgn[o + 2] * comp[gidx[o + 2]];
                r3 += gsgn[o + 3] * comp[gidx[o + 3]];
            }
            v = make_float4(r0, r1, r2, r3);
        }
        out4[idx] = v;                          // plain cached store
    }

    // Trace scalar at index DIMN*DIMN: block 0 warp 0, one diagonal element
    // per lane, shuffle-reduce (fixed order -> deterministic).
    if (blockIdx.x == 0 && threadIdx.x < 32) {
        const int t = threadIdx.x;
        float d = 0.f;
        #pragma unroll
        for (int k = 0; k < MD; k++) {
            const int o = k * (MD * MD) + t * MD + t;
            d += gsgn[o] * comp[gidx[o]];
        }
        #pragma unroll
        for (int off = 16; off > 0; off >>= 1)
            d += __shfl_down_sync(0xFFFFFFFFu, d, off);
        if (t == 0) out[(size_t)DIMN * DIMN] = d;
    }
}

extern "C" void kernel_launch(void* const* d_in, const int* in_sizes, int n_in,
                              void* d_out, int out_size)
{
    const float* comp = (const float*)d_in[0];   // components [10000] f32
    const int*   gidx = (const int*)  d_in[1];   // gather_idx [32,32,32] i32
    const float* gsgn = (const float*)d_in[2];   // gather_sign [32,32,32] f32

    float* out = (float*)d_out;

    ricci_fused2_kernel<<<GRID, TPB>>>(comp, gidx, gsgn, out);
}

// round 8
// speedup vs baseline: 1.0141x; 1.0141x over previous
#include <cuda_runtime.h>

// dim=4096, MAX_DIM=32, N_COMP=10000.
// gather_idx/gather_sign: [32,32,32] row-major (k,i,j), int32/float32.
// Output: ricci[4096*4096] row-major + scalar trace at index 4096*4096.

#define DIMN  4096
#define MD    32
#define NCMP  10000

// One block per row i in [0,32). Strategy: convert the chained gather
// (LDG idx -> LDG comp[idx]) into ONE global round trip by staging comp
// and this row's idx/sgn tables in shared, then gathering via LDS only.
// Each block writes its FULL 4096-float output row. Block 0 warp 1 also
// computes the trace scalar (diagonal tables prefetched to registers
// before the sync; comp gathered from shared).
__global__ __launch_bounds__(256)
void ricci_patch3_kernel(const float* __restrict__ comp,
                         const int*   __restrict__ gidx,
                         const float* __restrict__ gsgn,
                         float* __restrict__ out)
{
    __shared__ float scomp[NCMP];      // 40000 B
    __shared__ int   sidx[MD * MD];    //  4096 B
    __shared__ float ssgn[MD * MD];    //  4096 B
    __shared__ float srow[MD];         //   128 B

    const int i = blockIdx.x;          // row 0..31
    const int t = threadIdx.x;         // 0..255

    // Stage comp (coalesced, independent).
    for (int n = t; n < NCMP; n += 256) scomp[n] = comp[n];

    // Stage this row's [k][j] tables: element (k,i,j) at k*1024 + i*32 + j.
    {
        const int base = i * MD;
        #pragma unroll
        for (int n = t; n < MD * MD; n += 256) {
            const int g = (n >> 5) * (MD * MD) + base + (n & 31);
            sidx[n] = gidx[g];
            ssgn[n] = gsgn[g];
        }
    }

    // Block 0, warp 1: prefetch diagonal tables (k, t, t) into registers —
    // independent LDGs, overlapped with the staging round trip above.
    float dsgn[MD];
    int   didx[MD];
    const bool diag_warp = (blockIdx.x == 0) && (t >= 32) && (t < 64);
    if (diag_warp) {
        const int r = t - 32;          // diagonal row handled by this lane
        #pragma unroll
        for (int k = 0; k < MD; k++) {
            const int g = k * (MD * MD) + r * MD + r;
            didx[k] = gidx[g];
            dsgn[k] = gsgn[g];
        }
    }

    __syncthreads();

    // Gather-reduce for this row (threads 0..31), all from shared.
    if (t < MD) {
        float r = 0.f;
        #pragma unroll
        for (int k = 0; k < MD; k++) {
            const int n = k * MD + t;
            r += ssgn[n] * scomp[sidx[n]];
        }
        srow[t] = r;
    }

    // Trace scalar: warp 1 of block 0, one diagonal row per lane.
    if (diag_warp) {
        float d = 0.f;
        #pragma unroll
        for (int k = 0; k < MD; k++) d += dsgn[k] * scomp[didx[k]];
        #pragma unroll
        for (int off = 16; off > 0; off >>= 1)
            d += __shfl_down_sync(0xFFFFFFFFu, d, off);
        if (t == 32) out[(size_t)DIMN * DIMN] = d;
    }

    __syncthreads();

    // Write the full row: values in cols 0..31, zeros elsewhere.
    float4* __restrict__ row4 =
        reinterpret_cast<float4*>(out + (size_t)i * DIMN);
    #pragma unroll
    for (int c = t; c < DIMN / 4; c += 256) {
        float4 v;
        if (c < MD / 4) {
            const int j = c * 4;
            v = make_float4(srow[j], srow[j + 1], srow[j + 2], srow[j + 3]);
        } else {
            v = make_float4(0.f, 0.f, 0.f, 0.f);
        }
        row4[c] = v;
    }
}

extern "C" void kernel_launch(void* const* d_in, const int* in_sizes, int n_in,
                              void* d_out, int out_size)
{
    const float* comp = (const float*)d_in[0];   // components [10000] f32
    const int*   gidx = (const int*)  d_in[1];   // gather_idx [32,32,32] i32
    const float* gsgn = (const float*)d_in[2];   // gather_sign [32,32,32] f32

    float* out = (float*)d_out;

    // Patch FIRST (rows 0..31 + trace scalar), then fill the disjoint
    // remainder (rows 32..4095) with the driver's memset path. Same stream:
    // the order lets the big memset hide behind/after the tiny kernel
    // instead of inflating its gather latency.
    ricci_patch3_kernel<<<MD, 256>>>(comp, gidx, gsgn, out);

    const size_t skip = (size_t)MD * DIMN;                 // 32*4096 floats
    const size_t fill = (size_t)DIMN * DIMN - skip;
    cudaMemsetAsync(out + skip, 0, fill * sizeof(float));
}

// round 9
// speedup vs baseline: 1.2801x; 1.2623x over previous
#include <cuda_runtime.h>
#include <cstdint>

// dim=4096, MAX_DIM=32, N_COMP=10000.
// gather_idx/gather_sign: [32,32,32] row-major (k,i,j), int32/float32.
// Output: ricci[4096*4096] row-major + scalar trace at index 4096*4096.

#define DIMN 4096
#define MD   32
#define TPB  256

// Block geometry:
//   blocks 0..15   : patch blocks, 2 rows each (rows 0..31), one 32KB bulk store
//   blocks 16..523 : fill blocks, 128KB each (4 x 32KB bulk stores of zeros)
#define PATCH_BLKS 16
#define FILL_BLKS  508                  // (4096-32) rows * 16KB / 128KB
#define GRID       (PATCH_BLKS + FILL_BLKS)
#define SBUF_FLOATS 8192                // 32KB

__device__ __forceinline__ void bulk_store(float* gdst, uint32_t ssrc, uint32_t bytes)
{
    asm volatile(
        "cp.async.bulk.global.shared::cta.bulk_group [%0], [%1], %2;"
        :: "l"(gdst), "r"(ssrc), "r"(bytes) : "memory");
}

__global__ __launch_bounds__(TPB)
void ricci_tma_kernel(const float* __restrict__ comp,
                      const int*   __restrict__ gidx,
                      const float* __restrict__ gsgn,
                      float* __restrict__ out)
{
    __shared__ __align__(128) float sbuf[SBUF_FLOATS];   // 32KB

    const int b = blockIdx.x;
    const int t = threadIdx.x;

    // Zero the SMEM buffer (8 float4 per thread).
    float4* s4 = reinterpret_cast<float4*>(sbuf);
    #pragma unroll
    for (int n = t; n < SBUF_FLOATS / 4; n += TPB)
        s4[n] = make_float4(0.f, 0.f, 0.f, 0.f);
    __syncthreads();

    const uint32_t sbase = (uint32_t)__cvta_generic_to_shared(sbuf);

    if (b < PATCH_BLKS) {
        // Patch block: rows 2b and 2b+1. Threads 0..63 compute one element.
        if (t < 64) {
            const int i = 2 * b + (t >> 5);
            const int j = t & 31;
            float r = 0.f;
            #pragma unroll
            for (int k = 0; k < MD; k++) {
                const int o = k * (MD * MD) + i * MD + j;
                r += gsgn[o] * comp[gidx[o]];
            }
            sbuf[(t >> 5) * DIMN + j] = r;
        }

        // Block 0, warp 2 (threads 64..95): trace scalar.
        if (b == 0 && t >= 64 && t < 96) {
            const int d = t - 64;
            float s = 0.f;
            #pragma unroll
            for (int k = 0; k < MD; k++) {
                const int o = k * (MD * MD) + d * MD + d;
                s += gsgn[o] * comp[gidx[o]];
            }
            #pragma unroll
            for (int off = 16; off > 0; off >>= 1)
                s += __shfl_down_sync(0xFFFFFFFFu, s, off);
            if (d == 0) out[(size_t)DIMN * DIMN] = s;
        }

        __syncthreads();
        if (t == 0) {
            asm volatile("fence.proxy.async.shared::cta;" ::: "memory");
            bulk_store(out + (size_t)b * SBUF_FLOATS, sbase,
                       SBUF_FLOATS * sizeof(float));
            asm volatile("cp.async.bulk.commit_group;" ::: "memory");
            asm volatile("cp.async.bulk.wait_group 0;" ::: "memory");
        }
    } else {
        // Fill block: 128KB of zeros = 4 bulk stores from the same buffer.
        if (t == 0) {
            asm volatile("fence.proxy.async.shared::cta;" ::: "memory");
            float* gbase = out + (size_t)MD * DIMN
                         + (size_t)(b - PATCH_BLKS) * (4 * SBUF_FLOATS);
            #pragma unroll
            for (int c = 0; c < 4; c++)
                bulk_store(gbase + (size_t)c * SBUF_FLOATS, sbase,
                           SBUF_FLOATS * sizeof(float));
            asm volatile("cp.async.bulk.commit_group;" ::: "memory");
            asm volatile("cp.async.bulk.wait_group 0;" ::: "memory");
        }
    }
    // Keep SMEM alive until the issuing thread's bulk reads complete.
    __syncthreads();
}

extern "C" void kernel_launch(void* const* d_in, const int* in_sizes, int n_in,
                              void* d_out, int out_size)
{
    const float* comp = (const float*)d_in[0];   // components [10000] f32
    const int*   gidx = (const int*)  d_in[1];   // gather_idx [32,32,32] i32
    const float* gsgn = (const float*)d_in[2];   // gather_sign [32,32,32] f32

    float* out = (float*)d_out;

    ricci_tma_kernel<<<GRID, TPB>>>(comp, gidx, gsgn, out);
}

// round 10
// speedup vs baseline: 1.3465x; 1.0519x over previous
#include <cuda_runtime.h>
#include <cstdint>

// dim=4096, MAX_DIM=32, N_COMP=10000.
// gather_idx/gather_sign: [32,32,32] row-major (k,i,j), int32/float32.
// Output: ricci[4096*4096] row-major + scalar trace at index 4096*4096.

#define DIMN 4096
#define MD   32
#define TPB  256

// Single-wave geometry (<=148 SMs):
//   blocks 0..15   : patch blocks, 2 rows each (rows 0..31) -> 1 x 32KB store
//   blocks 16..142 : fill blocks, 32 rows each (rows 32..4095) -> 16 x 32KB
#define PATCH_BLKS 16
#define FILL_BLKS  127
#define GRID       (PATCH_BLKS + FILL_BLKS)      // 143
#define SBUF_FLOATS 8192                          // 32KB
#define FILL_STORES 16                            // 512KB per fill block

__device__ __forceinline__ void bulk_store(float* gdst, uint32_t ssrc, uint32_t bytes)
{
    asm volatile(
        "cp.async.bulk.global.shared::cta.bulk_group [%0], [%1], %2;"
        :: "l"(gdst), "r"(ssrc), "r"(bytes) : "memory");
}

__global__ __launch_bounds__(TPB)
void ricci_tma2_kernel(const float* __restrict__ comp,
                       const int*   __restrict__ gidx,
                       const float* __restrict__ gsgn,
                       float* __restrict__ out)
{
    __shared__ __align__(128) float sbuf[SBUF_FLOATS];   // 32KB

    const int b = blockIdx.x;
    const int t = threadIdx.x;

    // Zero the SMEM buffer (8 float4 per thread).
    float4* s4 = reinterpret_cast<float4*>(sbuf);
    #pragma unroll
    for (int n = t; n < SBUF_FLOATS / 4; n += TPB)
        s4[n] = make_float4(0.f, 0.f, 0.f, 0.f);

    const uint32_t sbase = (uint32_t)__cvta_generic_to_shared(sbuf);

    if (b >= PATCH_BLKS) {
        // Fill block: 512KB of zeros, 16 bulk stores from the same buffer.
        __syncthreads();
        if (t == 0) {
            asm volatile("fence.proxy.async.shared::cta;" ::: "memory");
            float* gbase = out + (size_t)MD * DIMN
                         + (size_t)(b - PATCH_BLKS) * (FILL_STORES * SBUF_FLOATS);
            #pragma unroll
            for (int c = 0; c < FILL_STORES; c++)
                bulk_store(gbase + (size_t)c * SBUF_FLOATS, sbase,
                           SBUF_FLOATS * sizeof(float));
            asm volatile("cp.async.bulk.commit_group;" ::: "memory");
            // Wait only for the SMEM source reads (CUTLASS-style); write
            // visibility is guaranteed at the kernel boundary.
            asm volatile("cp.async.bulk.wait_group.read 0;" ::: "memory");
        }
        __syncthreads();
        return;
    }

    // Patch block: rows 2b and 2b+1. Threads 0..63 compute one element.
    if (t < 64) {
        const int i = 2 * b + (t >> 5);
        const int j = t & 31;
        float r = 0.f;
        #pragma unroll
        for (int k = 0; k < MD; k++) {
            const int o = k * (MD * MD) + i * MD + j;
            r += gsgn[o] * comp[gidx[o]];
        }
        sbuf[(t >> 5) * DIMN + j] = r;
    }

    // Block 0, warp 2 (threads 64..95): trace scalar via shuffle reduce
    // (fixed order -> deterministic). Scalar is outside the bulk region.
    if (b == 0 && t >= 64 && t < 96) {
        const int d = t - 64;
        float s = 0.f;
        #pragma unroll
        for (int k = 0; k < MD; k++) {
            const int o = k * (MD * MD) + d * MD + d;
            s += gsgn[o] * comp[gidx[o]];
        }
        #pragma unroll
        for (int off = 16; off > 0; off >>= 1)
            s += __shfl_down_sync(0xFFFFFFFFu, s, off);
        if (d == 0) out[(size_t)DIMN * DIMN] = s;
    }

    __syncthreads();
    if (t == 0) {
        asm volatile("fence.proxy.async.shared::cta;" ::: "memory");
        bulk_store(out + (size_t)b * SBUF_FLOATS, sbase,
                   SBUF_FLOATS * sizeof(float));
        asm volatile("cp.async.bulk.commit_group;" ::: "memory");
        asm volatile("cp.async.bulk.wait_group.read 0;" ::: "memory");
    }
    __syncthreads();
}

extern "C" void kernel_launch(void* const* d_in, const int* in_sizes, int n_in,
                              void* d_out, int out_size)
{
    const float* comp = (const float*)d_in[0];   // components [10000] f32
    const int*   gidx = (const int*)  d_in[1];   // gather_idx [32,32,32] i32
    const float* gsgn = (const float*)d_in[2];   // gather_sign [32,32,32] f32

    float* out = (float*)d_out;

    ricci_tma2_kernel<<<GRID, TPB>>>(comp, gidx, gsgn, out);
}

// round 11
// speedup vs baseline: 1.4327x; 1.0640x over previous
#include <cuda_runtime.h>
#include <cstdint>

// dim=4096, MAX_DIM=32, N_COMP=10000.
// gather_idx/gather_sign: [32,32,32] row-major (k,i,j), int32/float32.
// Output: ricci[4096*4096] row-major + scalar trace at index 4096*4096.

#define DIMN 4096
#define MD   32
#define TPB  256

// Geometry (~2 blocks/SM):
//   blocks 0..15   : patch blocks, 2 rows each (rows 0..31) -> 1 x 32KB store
//   blocks 16..269 : fill blocks, 8 x 32KB = 256KB each (rows 32..4095)
//                    254 * 8 = 2032 chunks = 63.5MB exactly.
#define PATCH_BLKS 16
#define FILL_BLKS  254
#define GRID       (PATCH_BLKS + FILL_BLKS)      // 270
#define SBUF_FLOATS 8192                          // 32KB
#define FILL_STORES 8

__device__ __forceinline__ void bulk_store(float* gdst, uint32_t ssrc, uint32_t bytes)
{
    asm volatile(
        "cp.async.bulk.global.shared::cta.bulk_group [%0], [%1], %2;"
        :: "l"(gdst), "r"(ssrc), "r"(bytes) : "memory");
}

__global__ __launch_bounds__(TPB)
void ricci_tma3_kernel(const float* __restrict__ comp,
                       const int*   __restrict__ gidx,
                       const float* __restrict__ gsgn,
                       float* __restrict__ out)
{
    __shared__ __align__(128) float sbuf[SBUF_FLOATS];   // 32KB

    const int b = blockIdx.x;
    const int t = threadIdx.x;

    // Zero the SMEM buffer (8 float4 per thread).
    float4* s4 = reinterpret_cast<float4*>(sbuf);
    #pragma unroll
    for (int n = t; n < SBUF_FLOATS / 4; n += TPB)
        s4[n] = make_float4(0.f, 0.f, 0.f, 0.f);

    const uint32_t sbase = (uint32_t)__cvta_generic_to_shared(sbuf);

    if (b >= PATCH_BLKS) {
        // Fill block: 8 x 32KB bulk stores, issued by 8 DIFFERENT warps in
        // parallel (one bulk-group per issuing thread) to deepen the TMA
        // queue instead of serializing through a single thread.
        __syncthreads();
        if ((t & 31) == 0) {
            const int w = t >> 5;                 // 0..7
            asm volatile("fence.proxy.async.shared::cta;" ::: "memory");
            float* gdst = out + (size_t)MD * DIMN
                        + ((size_t)(b - PATCH_BLKS) * FILL_STORES + w) * SBUF_FLOATS;
            bulk_store(gdst, sbase, SBUF_FLOATS * sizeof(float));
            asm volatile("cp.async.bulk.commit_group;" ::: "memory");
            // Wait only for the SMEM source read; write visibility is
            // guaranteed at the kernel boundary.
            asm volatile("cp.async.bulk.wait_group.read 0;" ::: "memory");
        }
        __syncthreads();
        return;
    }

    // Patch block: rows 2b and 2b+1. Threads 0..63 compute one element.
    if (t < 64) {
        const int i = 2 * b + (t >> 5);
        const int j = t & 31;
        float r = 0.f;
        #pragma unroll
        for (int k = 0; k < MD; k++) {
            const int o = k * (MD * MD) + i * MD + j;
            r += gsgn[o] * comp[gidx[o]];
        }
        sbuf[(t >> 5) * DIMN + j] = r;
    }

    // Block 0, warp 2 (threads 64..95): trace scalar via shuffle reduce
    // (fixed order -> deterministic). Scalar lies outside the bulk region.
    if (b == 0 && t >= 64 && t < 96) {
        const int d = t - 64;
        float s = 0.f;
        #pragma unroll
        for (int k = 0; k < MD; k++) {
            const int o = k * (MD * MD) + d * MD + d;
            s += gsgn[o] * comp[gidx[o]];
        }
        #pragma unroll
        for (int off = 16; off > 0; off >>= 1)
            s += __shfl_down_sync(0xFFFFFFFFu, s, off);
        if (d == 0) out[(size_t)DIMN * DIMN] = s;
    }

    __syncthreads();
    if (t == 0) {
        asm volatile("fence.proxy.async.shared::cta;" ::: "memory");
        bulk_store(out + (size_t)b * SBUF_FLOATS, sbase,
                   SBUF_FLOATS * sizeof(float));
        asm volatile("cp.async.bulk.commit_group;" ::: "memory");
        asm volatile("cp.async.bulk.wait_group.read 0;" ::: "memory");
    }
    __syncthreads();
}

extern "C" void kernel_launch(void* const* d_in, const int* in_sizes, int n_in,
                              void* d_out, int out_size)
{
    const float* comp = (const float*)d_in[0];   // components [10000] f32
    const int*   gidx = (const int*)  d_in[1];   // gather_idx [32,32,32] i32
    const float* gsgn = (const float*)d_in[2];   // gather_sign [32,32,32] f32

    float* out = (float*)d_out;

    ricci_tma3_kernel<<<GRID, TPB>>>(comp, gidx, gsgn, out);
}